// round 16
// baseline (speedup 1.0000x reference)
#include <cuda_runtime.h>
#include <cstdint>

#define NH      128
#define NCODES  512
#define NCELLS  65536
#define NCOARSE 4096                   // 16 fine cells per coarse cell
#define XMIN    (-5.75f)
#define XMAX    (5.75f)
#define CW      (11.5f / 65536.0f)
#define INV_CW  (65536.0f / 11.5f)
#define FULLM   0xffffffffu

__device__ __forceinline__ float neg_inf() { return __int_as_float(0xff800000); }
__device__ __forceinline__ float pos_inf() { return __int_as_float(0x7f800000); }

// -------- device scratch (no allocation allowed) --------
__device__ float    g_ksort[NH];        // sorted kink positions (+inf padded)
__device__ int      g_actRank[NH];      // rank for activity test (128 = never)
__device__ int      g_sgn[NH];
__device__ float    g_w2t[NH * NCODES]; // transposed w2: [j][code]
__device__ float    g_A[129 * NCODES];  // per-interval intercepts
__device__ float    g_B[129 * NCODES];  // per-interval slopes
__device__ float    g_score[NCODES];    // dec_w . emb[c]
__device__ float    g_decb;
__device__ unsigned char g_kinkNear[NCELLS];   // set-only, deterministic per replay
__device__ unsigned short g_cellEnc[NCELLS];   // 0x8000 bad | 0x4000 split | idx
__device__ unsigned short g_coarseEnc[NCOARSE];// coarse: idx, or 0x8000 = consult fine
__device__ float4   g_spAB[NCELLS];     // split cells: (Amin,Bmin,Amax,Bmax)
__device__ unsigned g_spIdx[NCELLS];    // split cells: minIdx | maxIdx<<16

// ======== kernel 1 (k_pre): blocks 0..63 transpose w2, block 64 ranks/kinks,
//          blocks 65..128 scores ========
__global__ void k_pre(const float* __restrict__ w1, const float* __restrict__ b1,
                      const float* __restrict__ w2, const float* __restrict__ emb,
                      const float* __restrict__ dec_w, const float* __restrict__ dec_b)
{
    int blk = blockIdx.x;
    int t = threadIdx.x;                 // 256 threads
    if (blk < 64) {
        // ---- 32x32 tile transpose: w2[512][128] -> w2t[128][512] ----
        __shared__ float tl[32][33];
        int tj = blk & 3, tc = blk >> 2;           // j-tile 0..3, c-tile 0..15
        int tx = t & 31, ty = t >> 5;              // 8 rows per pass
        #pragma unroll
        for (int r = 0; r < 4; r++) {
            int row = ty + r * 8;                  // c within tile
            tl[row][tx] = w2[(tc * 32 + row) * NH + tj * 32 + tx];   // coalesced
        }
        __syncthreads();
        #pragma unroll
        for (int r = 0; r < 4; r++) {
            int row = ty + r * 8;                  // j within tile
            g_w2t[(tj * 32 + row) * NCODES + tc * 32 + tx] = tl[tx][row]; // coalesced
        }
    } else if (blk == 64) {
        // ---- sorted kinks + ranks/signs + kink-adjacent flags + decoder bias ----
        __shared__ float skv[NH];
        if (t < NH) {
            float w = w1[t], b = b1[t];
            skv[t] = (w != 0.0f) ? (-b / w) : pos_inf();
        }
        __syncthreads();
        if (t < NH) {
            float kv = skv[t];
            int r = 0;
            #pragma unroll 8
            for (int k = 0; k < NH; k++) {
                float o = skv[k];
                r += (o < kv) || (o == kv && k < t);   // unique rank, index tiebreak
            }
            g_ksort[r] = kv;
            float w = w1[t], b = b1[t];
            g_actRank[t] = (w != 0.0f) ? r : NH;
            g_sgn[t] = (w > 0.0f) ? 1 : ((w < 0.0f) ? -1 : ((b > 0.0f) ? -1 : 1));
            if (kv >= XMIN - 2.0f * CW && kv < XMAX + 2.0f * CW) {
                int g = (int)floorf((kv - XMIN) * INV_CW);
                #pragma unroll
                for (int d = -1; d <= 1; d++) {
                    int c = g + d;
                    if (c >= 0 && c < NCELLS) g_kinkNear[c] = 1;
                }
            }
        }
        if (t == 0) g_decb = dec_b[0];
    } else {
        // ---- score[c] = dec_w . emb[c]; 64 blocks x 8 warps = 512 warps ----
        int code = (blk - 65) * 8 + (t >> 5);
        int lane = t & 31;
        const float* er = emb + code * 256;
        float s = 0.0f;
        #pragma unroll
        for (int k = 0; k < 8; k++) {
            int d = lane + (k << 5);
            s = fmaf(dec_w[d], er[d], s);
        }
        #pragma unroll
        for (int off = 16; off >= 1; off >>= 1)
            s += __shfl_down_sync(FULLM, s, off);
        if (lane == 0) g_score[code] = s;
    }
}

// ======== kernel 2 (k_ab): block = interval, thread = code, coalesced w2t stream ====
__global__ void k_ab(const float* __restrict__ w1, const float* __restrict__ b1,
                     const float* __restrict__ b2)
{
    __shared__ float sbm[NH], swm[NH];
    int t = threadIdx.x;                 // 512 threads = code
    int i = blockIdx.x;                  // interval 0..128
    if (t < NH) {
        int r = g_actRank[t], s = g_sgn[t];
        bool act = (s > 0) ? (r < i) : (r >= i);
        sbm[t] = act ? b1[t] : 0.0f;
        swm[t] = act ? w1[t] : 0.0f;
    }
    __syncthreads();
    float A = b2[t], Bv = 0.0f;
    const float* wt = g_w2t + t;
    #pragma unroll 8
    for (int j = 0; j < NH; j++) {
        float v = wt[j * NCODES];        // coalesced: one 128B line per warp-LDG
        A  = fmaf(v, sbm[j], A);         // fmaf(v,0,A)==A exactly: bit-identical sums
        Bv = fmaf(v, swm[j], Bv);
    }
    g_A[i * NCODES + t] = A;
    g_B[i * NCODES + t] = Bv;
}

__device__ __forceinline__ int find_interval(const float* sk, float x) {
    int lo = 0, hi = NH;
    #pragma unroll
    for (int it = 0; it < 8; it++) {
        if (lo < hi) {
            int mid = (lo + hi) >> 1;
            if (sk[mid] <= x) lo = mid + 1; else hi = mid;
        }
    }
    return lo;   // number of kinks <= x, in [0,128]
}

// exact 512-line argmax from GLOBAL tables (rare fallback path in k_main)
__device__ __forceinline__ void scan512(const float* __restrict__ Ar,
                                        const float* __restrict__ Br,
                                        float xv, int lane, int& out_idx)
{
    float best = neg_inf(); int bi = 0;
    #pragma unroll
    for (int k = 0; k < 16; k++) {
        int c = lane + (k << 5);
        float v = fmaf(Br[c], xv, Ar[c]);
        if (v > best) { best = v; bi = c; }        // ascending c -> first-max per lane
    }
    #pragma unroll
    for (int off = 16; off >= 1; off >>= 1) {
        float ov = __shfl_down_sync(FULLM, best, off);
        int   oi = __shfl_down_sync(FULLM, bi,  off);
        if (ov > best || (ov == best && oi < bi)) { best = ov; bi = oi; }
    }
    out_idx = __shfl_sync(FULLM, bi, 0);           // jnp.argmax first-index semantics
}

// ======== kernel 3: coarse-to-fine classification; bad leaves get 2-line
// split certification (convex envelope pinched at two points => exactly two lines).
__global__ void k_classify()
{
    __shared__ float sk[NH];
    int tid = threadIdx.x;
    if (tid < NH) sk[tid] = g_ksort[tid];
    __syncthreads();
    int wg = blockIdx.x * (blockDim.x >> 5) + (tid >> 5);
    if (wg >= NCOARSE) return;
    int lane = tid & 31;

    float a[16], b[16];
    int iload = -1;
    int ivCur = 0;

    auto evalAt = [&](float x) -> int {          // warp-cooperative 512-line argmax
        int iv = find_interval(sk, x);           // warp-uniform
        if (iv != iload) {
            const float* Ar = g_A + iv * NCODES + lane;
            const float* Br = g_B + iv * NCODES + lane;
            #pragma unroll
            for (int k = 0; k < 16; k++) { a[k] = Ar[k << 5]; b[k] = Br[k << 5]; }
            iload = iv;
        }
        ivCur = iv;
        float best = neg_inf(); int bi = 0;
        #pragma unroll
        for (int k = 0; k < 16; k++) {
            float v = fmaf(b[k], x, a[k]);
            if (v > best) { best = v; bi = lane + (k << 5); }
        }
        #pragma unroll
        for (int off = 16; off >= 1; off >>= 1) {
            float ov = __shfl_down_sync(FULLM, best, off);
            int   oi = __shfl_down_sync(FULLM, bi,  off);
            if (ov > best || (ov == best && oi < bi)) { best = ov; bi = oi; }
        }
        return __shfl_sync(FULLM, bi, 0);
    };
    auto evalEdge = [&](int e) -> int { return evalAt(XMIN + (float)e * CW); };

    int loE = wg * 16, hiE = loE + 16;
    int argL = evalEdge(loE); int ivL = ivCur;
    int argR = evalEdge(hiE); int ivR = ivCur;

    unsigned char kn = (lane < 16) ? g_kinkNear[loE + lane] : 0;
    unsigned kmask = __ballot_sync(FULLM, kn != 0);
    bool anyKink = (kmask & 0xffffu) != 0;

    if (argL == argR && ivL == ivR) {
        if (lane < 16)
            g_cellEnc[loE + lane] =
                (unsigned short)(argL | (kn ? 0x8000 : 0));
        if (lane == 0)
            g_coarseEnc[wg] =
                (unsigned short)(anyKink ? 0x8000 : argL);
        return;
    }
    if (lane == 0) g_coarseEnc[wg] = 0x8000;     // dirty: consult fine table

    auto fill = [&](int lo, int hi, int arg) {
        int cell = lo + lane;
        if (cell < hi)
            g_cellEnc[cell] =
                (unsigned short)(arg | (g_kinkNear[cell] ? 0x8000 : 0));
    };
    // warp-uniform bisection stack (depth <= 4)
    int sLo[8], sHi[8], sAL[8], sAH[8], sIL[8], sIH[8];
    sLo[0] = loE; sHi[0] = hiE; sAL[0] = argL; sAH[0] = argR;
    sIL[0] = ivL; sIH[0] = ivR;
    int sp = 1;
    while (sp) {
        sp--;
        int lo = sLo[sp], hi = sHi[sp];
        int aL = sAL[sp], aH = sAH[sp], iL = sIL[sp], iH = sIH[sp];
        if (aL == aH && iL == iH) { fill(lo, hi, aL); continue; }
        if (hi - lo == 1) {
            // leaf bad cell: try exact 2-line split certification
            bool kink = g_kinkNear[lo] != 0;     // warp-uniform load
            bool done = false;
            if (!kink && aL != aH && iL == iH) {
                float AL = g_A[iL * NCODES + aL], BL = g_B[iL * NCODES + aL];
                float AH = g_A[iL * NCODES + aH], BH = g_B[iL * NCODES + aH];
                float dB = BL - BH;
                float xlo = XMIN + (float)lo * CW;
                float xhi = xlo + CW;
                if (dB != 0.0f) {
                    float xs = (AH - AL) / dB;
                    if (xs > xlo && xs < xhi) {
                        int aM = evalAt(xs);
                        if (aM == aL || aM == aH) {
                            // envelope == {line aL, line aH} on this cell (exact)
                            if (lane == 0) {
                                int mn = (aL < aH) ? aL : aH;
                                int mx = (aL < aH) ? aH : aL;
                                float Amn = (mn == aL) ? AL : AH;
                                float Bmn = (mn == aL) ? BL : BH;
                                float Amx = (mn == aL) ? AH : AL;
                                float Bmx = (mn == aL) ? BH : BL;
                                g_spAB[lo] = make_float4(Amn, Bmn, Amx, Bmx);
                                g_spIdx[lo] = (unsigned)mn | ((unsigned)mx << 16);
                                g_cellEnc[lo] = (unsigned short)0x4000;
                            }
                            done = true;
                        }
                    }
                }
            }
            if (!done && lane == 0)
                g_cellEnc[lo] = (unsigned short)(aL | 0x8000);
            continue;
        }
        int mid = (lo + hi) >> 1;
        int aM = evalEdge(mid);
        int iM = ivCur;
        sLo[sp] = lo;  sHi[sp] = mid; sAL[sp] = aL; sAH[sp] = aM;
        sIL[sp] = iL;  sIH[sp] = iM;  sp++;
        sLo[sp] = mid; sHi[sp] = hi;  sAL[sp] = aM; sAH[sp] = aH;
        sIL[sp] = iM;  sIH[sp] = iH;  sp++;
    }
}

// ======== kernel 4: smem coarse fast path; split cells per-thread; scan only
//          for kink/multi-line cells ========
__global__ void k_main(const float* __restrict__ x_in, float* __restrict__ out,
                       int n, int write_idx)
{
    __shared__ unsigned short s_co[NCOARSE];     // 8 KB coarse table
    __shared__ float s_sc[NCODES];               // 2 KB score LUT
    __shared__ float s_sk[NH];
    int tid = threadIdx.x;                       // 256 threads
    {
        const uint4* src = (const uint4*)g_coarseEnc;
        uint4* dst = (uint4*)s_co;
        dst[tid] = src[tid];
        dst[tid + 256] = src[tid + 256];
    }
    s_sc[tid] = g_score[tid];
    s_sc[tid + 256] = g_score[tid + 256];
    if (tid < NH) s_sk[tid] = g_ksort[tid];
    __syncthreads();
    float db = g_decb;

    int b = blockIdx.x * blockDim.x + tid;
    bool active = b < n;
    float x = 0.0f;
    if (active) x = x_in[b];

    int idx = 0;
    bool inR = active && x >= XMIN && x < XMAX;
    int g = 0;
    bool fine = false;
    if (inR) {
        g = (int)((x - XMIN) * INV_CW);
        if (g >= NCELLS) g = NCELLS - 1;
        unsigned ce = s_co[g >> 4];              // smem: no global dependency
        idx = ce & 511;
        fine = (ce & 0x8000u) != 0;
    }
    bool need = active && !inR;                  // out-of-range -> direct fallback
    if (fine) {
        unsigned fe = g_cellEnc[g];              // random L2 load, small fraction
        if (fe & 0x8000u) {
            idx = fe & 511;
            need = true;                         // exact scan required
        } else if (fe & 0x4000u) {
            // exact 2-line split cell: same comparison scan512 would make
            float4 sp = g_spAB[g];
            unsigned pi = g_spIdx[g];
            float vmn = fmaf(sp.y, x, sp.x);
            float vmx = fmaf(sp.w, x, sp.z);
            idx = (vmn >= vmx) ? (int)(pi & 0xffffu) : (int)(pi >> 16);
        } else {
            idx = fe & 511;
        }
    }

    int lane = tid & 31;
    unsigned m = __ballot_sync(FULLM, need);
    while (m) {                                  // whole warp per fallback element
        int src = __ffs(m) - 1; m &= m - 1;
        float xb = __shfl_sync(FULLM, x, src);
        int ib = find_interval(s_sk, xb);        // warp-uniform
        int bi;
        scan512(g_A + ib * NCODES, g_B + ib * NCODES, xb, lane, bi);
        if (lane == src) idx = bi;
    }
    if (!active) return;
    out[b] = s_sc[idx] + db;
    if (write_idx) out[n + b] = (float)idx;
}

extern "C" void kernel_launch(void* const* d_in, const int* in_sizes, int n_in,
                              void* d_out, int out_size)
{
    const float* x     = (const float*)d_in[0];
    const float* w1    = (const float*)d_in[1];
    const float* b1    = (const float*)d_in[2];
    const float* w2    = (const float*)d_in[3];
    const float* b2    = (const float*)d_in[4];
    const float* emb   = (const float*)d_in[5];
    const float* dec_w = (const float*)d_in[6];
    const float* dec_b = (const float*)d_in[7];
    int n = in_sizes[0];
    float* out = (float*)d_out;

    k_pre<<<129, 256>>>(w1, b1, w2, emb, dec_w, dec_b);
    k_ab<<<129, 512>>>(w1, b1, b2);
    k_classify<<<NCOARSE / 8, 256>>>();
    int write_idx = (out_size >= 2 * n) ? 1 : 0;
    k_main<<<(n + 255) / 256, 256>>>(x, out, n, write_idx);
}